// round 1
// baseline (speedup 1.0000x reference)
#include <cuda_runtime.h>

#define B_ROWS 16384
#define NN     128
#define NS     1024
#define GRID_MAIN  296
#define BLOCK_MAIN 256
#define LANES (GRID_MAIN * 2)

// ---------------- scratch (device globals; no allocation) ----------------
__device__ float g_ns1[NN], g_ns2[NN], g_ncs[NN];
__device__ float g_ss1[NS], g_ss2[NS], g_scs[NS];
__device__ float g_sc[4];   // [0]=hier, [1]=nf, [2]=sf

__global__ void zero_kernel() {
    int i = threadIdx.x;
    if (i < NN) { g_ns1[i] = 0.f; g_ns2[i] = 0.f; g_ncs[i] = 0.f; }
    g_ss1[i] = 0.f; g_ss2[i] = 0.f; g_scs[i] = 0.f;
    if (i < 4) g_sc[i] = 0.f;
}

// softplus/sigmoid building blocks (3 MUFU per element)
struct Elem {
    float spx;   // softplus(x)
    float spm;   // softplus(-x)
    float p;     // sigmoid(x)
    float omp;   // 1 - sigmoid(x)
};
__device__ __forceinline__ Elem eval_elem(float x) {
    float ax = fabsf(x);
    float e  = __expf(-ax);              // EX2
    float L  = __logf(1.0f + e);         // LG2
    float q  = __fdividef(1.0f, 1.0f + e);  // RCP
    Elem r;
    r.spx = fmaxf(x, 0.0f) + L;
    r.spm = r.spx - x;
    bool pos = (x >= 0.0f);
    r.p   = pos ? q       : e * q;
    r.omp = pos ? e * q   : q;
    return r;
}

__global__ __launch_bounds__(BLOCK_MAIN, 2)
void main_kernel(const float* __restrict__ nlg, const float* __restrict__ slg,
                 const int* __restrict__ nlb,  const int* __restrict__ slb)
{
    const int tid  = threadIdx.x;
    const int n    = tid & 127;                    // narrative class owned
    const int lane = blockIdx.x * 2 + (tid >> 7);  // row-processor id

    float s1 = 0.f, s2 = 0.f, csn = 0.f;
    float t1[8], t2[8], css[8];
#pragma unroll
    for (int k = 0; k < 8; k++) { t1[k] = 0.f; t2[k] = 0.f; css[k] = 0.f; }
    float hier = 0.f, nf = 0.f, sf = 0.f;

    for (int r = lane; r < B_ROWS; r += LANES) {
        const size_t nb = (size_t)r * NN + n;
        float xn = nlg[nb];
        float g  = (float)nlb[nb];

        const size_t sb = (size_t)r * NS + n * 8;
        float4 v0 = *(const float4*)(slg + sb);
        float4 v1 = *(const float4*)(slg + sb + 4);
        int4   l0 = *(const int4*)(slb + sb);
        int4   l1 = *(const int4*)(slb + sb + 4);

        // ---- narrative element ----
        Elem en = eval_elem(xn);
        s1  = fmaf(g, en.spm, s1);
        s2  = fmaf(1.0f - g, en.spx, s2);
        csn += g;
        nf  = fmaf(g * en.omp * en.omp, -en.spm, nf);
        float pn = en.p;

        // ---- 8 subnarrative elements of this group ----
        float xs[8] = { v0.x, v0.y, v0.z, v0.w, v1.x, v1.y, v1.z, v1.w };
        float ls[8] = { (float)l0.x, (float)l0.y, (float)l0.z, (float)l0.w,
                        (float)l1.x, (float)l1.y, (float)l1.z, (float)l1.w };
        float mx = xs[0];
#pragma unroll
        for (int k = 0; k < 8; k++) {
            float x = xs[k];
            float s = ls[k];
            mx = fmaxf(mx, x);
            Elem es = eval_elem(x);
            t1[k]  = fmaf(g * s, es.spm, t1[k]);
            t2[k]  = fmaf(g - g * s, es.spx, t2[k]);
            css[k] += s;
            sf     = fmaf(s * es.omp * es.omp, -es.spm, sf);
        }

        // ---- hierarchy: max(sigmoid) == sigmoid(max) ----
        {
            float axm = fabsf(mx);
            float em  = __expf(-axm);
            float qm  = __fdividef(1.0f, 1.0f + em);
            float pm  = (mx >= 0.0f) ? qm : em * qm;
            hier = fmaf(g, fmaxf(pm - pn, 0.0f), hier);
        }
    }

    // ---------------- block reduction: pair the two 128-lane halves ----------------
    __shared__ float sh[128][31];   // 31 stride: avoid bank conflicts
    if (tid >= 128) {
        float* d = sh[tid - 128];
        d[0] = s1; d[1] = s2; d[2] = csn;
#pragma unroll
        for (int k = 0; k < 8; k++) { d[3 + k] = t1[k]; d[11 + k] = t2[k]; d[19 + k] = css[k]; }
        d[27] = hier; d[28] = nf; d[29] = sf;
    }
    __syncthreads();

    float hsum = 0.f, nfsum = 0.f, sfsum = 0.f;
    if (tid < 128) {
        float* d = sh[tid];
        s1 += d[0]; s2 += d[1]; csn += d[2];
#pragma unroll
        for (int k = 0; k < 8; k++) { t1[k] += d[3 + k]; t2[k] += d[11 + k]; css[k] += d[19 + k]; }
        hsum = hier + d[27]; nfsum = nf + d[28]; sfsum = sf + d[29];

        atomicAdd(&g_ns1[n], s1);
        atomicAdd(&g_ns2[n], s2);
        atomicAdd(&g_ncs[n], csn);
#pragma unroll
        for (int k = 0; k < 8; k++) {
            atomicAdd(&g_ss1[n * 8 + k], t1[k]);
            atomicAdd(&g_ss2[n * 8 + k], t2[k]);
            atomicAdd(&g_scs[n * 8 + k], css[k]);
        }
    }

    // scalar reduce over lower 128 threads (4 warps)
#pragma unroll
    for (int o = 16; o; o >>= 1) {
        hsum  += __shfl_down_sync(0xffffffffu, hsum,  o);
        nfsum += __shfl_down_sync(0xffffffffu, nfsum, o);
        sfsum += __shfl_down_sync(0xffffffffu, sfsum, o);
    }
    __shared__ float shw[3][4];
    __syncthreads();
    if (tid < 128 && (tid & 31) == 0) {
        int w = tid >> 5;
        shw[0][w] = hsum; shw[1][w] = nfsum; shw[2][w] = sfsum;
    }
    __syncthreads();
    if (tid == 0) {
        atomicAdd(&g_sc[0], shw[0][0] + shw[0][1] + shw[0][2] + shw[0][3]);
        atomicAdd(&g_sc[1], shw[1][0] + shw[1][1] + shw[1][2] + shw[1][3]);
        atomicAdd(&g_sc[2], shw[2][0] + shw[2][1] + shw[2][2] + shw[2][3]);
    }
}

__global__ void finalize_kernel(float* __restrict__ out) {
    int tid = threadIdx.x;  // 1024 threads

    // sub classes (all 1024)
    double sub_sum;
    {
        float cs = g_scs[tid];
        float pw = fminf(fmaxf((16384.0f - cs) / (cs + 1e-6f), 1.0f), 50.0f);
        sub_sum = (double)pw * (double)g_ss1[tid] + (double)g_ss2[tid];
    }
    double narr_sum = 0.0, valid = 0.0;
    if (tid < NN) {
        float cs = g_ncs[tid];
        float pw = fminf(fmaxf((16384.0f - cs) / (cs + 1e-6f), 1.0f), 50.0f);
        narr_sum = (double)pw * (double)g_ns1[tid] + (double)g_ns2[tid];
        valid    = (double)cs;
    }

#pragma unroll
    for (int o = 16; o; o >>= 1) {
        narr_sum += __shfl_down_sync(0xffffffffu, narr_sum, o);
        sub_sum  += __shfl_down_sync(0xffffffffu, sub_sum,  o);
        valid    += __shfl_down_sync(0xffffffffu, valid,    o);
    }
    __shared__ double red[96];
    int w = tid >> 5;  // 32 warps
    if ((tid & 31) == 0) { red[w] = narr_sum; red[32 + w] = sub_sum; red[64 + w] = valid; }
    __syncthreads();
    if (tid == 0) {
        double ns = 0.0, ss = 0.0, vv = 0.0;
        for (int i = 0; i < 32; i++) { ns += red[i]; ss += red[32 + i]; vv += red[64 + i]; }
        double narrative_loss = ns / (16384.0 * 128.0);
        double sub_loss = (vv > 0.0) ? (ss / 8.0) / fmax(vv, 1.0) : 0.0;
        double hier = (double)g_sc[0] / 16384.0;
        double nfv  = (double)g_sc[1] / (16384.0 * 128.0);
        double sfv  = (double)g_sc[2] / (16384.0 * 1024.0);
        double total = (narrative_loss - 0.1 * nfv)
                     + (sub_loss       - 0.1 * sfv)
                     + 0.5 * hier;
        out[0] = (float)total;
    }
}

extern "C" void kernel_launch(void* const* d_in, const int* in_sizes, int n_in,
                              void* d_out, int out_size)
{
    const float* nlg = (const float*)d_in[0];   // narrative_logits [B,128]
    const float* slg = (const float*)d_in[1];   // subnarrative_logits [B,1024]
    const int*   nlb = (const int*)d_in[2];     // narrative_labels [B,128]
    const int*   slb = (const int*)d_in[3];     // subnarrative_labels [B,1024]
    (void)in_sizes; (void)n_in; (void)out_size;

    zero_kernel<<<1, 1024>>>();
    main_kernel<<<GRID_MAIN, BLOCK_MAIN>>>(nlg, slg, nlb, slb);
    finalize_kernel<<<1, 1024>>>((float*)d_out);
}